// round 10
// baseline (speedup 1.0000x reference)
#include <cuda_runtime.h>
#include <cuda_bf16.h>

#define N_NODES 50000
#define N_EDGES 800000
#define D 64

// Scratch (no allocations allowed): ~25.8 MB of static device globals.
// __align__(16): red.global.add.v4.f32 / float4 ld+st require 16B alignment.
__device__ __align__(16) float g_agg[N_NODES * D];    // scatter-sum of edge_attr
__device__ __align__(16) float g_cnt[N_NODES];        // per-src edge counts
__device__ __align__(16) float g_nemb[N_NODES * D];   // sigmoid node embeddings
__device__ int g_is64;                                 // 1 = edge_index is int64

__device__ __forceinline__ int load_index(const void* ei, int pos, int is64) {
    if (is64) return (int)((const long long*)ei)[pos];
    return ((const int*)ei)[pos];
}

// ---------------------------------------------------------------------------
// k0: zero agg + cnt with float4 stores; block 0 also runs the int32/int64
// detection (int64 indices < 50000 -> all high words zero).
// ---------------------------------------------------------------------------
__global__ void k_zero(const int2* __restrict__ ei) {
    if (blockIdx.x == 0) {
        int local = 0;
        for (int i = threadIdx.x; i < 4096; i += blockDim.x)
            local |= ei[i].y;
        // warp-reduce then block-or via shared
        __shared__ int any_hi;
        if (threadIdx.x == 0) any_hi = 0;
        __syncthreads();
        local |= __shfl_xor_sync(0xffffffffu, local, 16);
        local |= __shfl_xor_sync(0xffffffffu, local, 8);
        local |= __shfl_xor_sync(0xffffffffu, local, 4);
        local |= __shfl_xor_sync(0xffffffffu, local, 2);
        local |= __shfl_xor_sync(0xffffffffu, local, 1);
        if ((threadIdx.x & 31) == 0 && local) any_hi = 1;
        __syncthreads();
        if (threadIdx.x == 0) g_is64 = (any_hi == 0) ? 1 : 0;
    }
    int i = blockIdx.x * blockDim.x + threadIdx.x;
    const int AGG4 = (N_NODES * D) / 4;   // 800000
    const int CNT4 = N_NODES / 4;         // 12500
    float4 z = make_float4(0.f, 0.f, 0.f, 0.f);
    if (i < AGG4) {
        reinterpret_cast<float4*>(g_agg)[i] = z;
    } else if (i < AGG4 + CNT4) {
        reinterpret_cast<float4*>(g_cnt)[i - AGG4] = z;
    }
}

// ---------------------------------------------------------------------------
// k1: scatter-add edge_attr rows onto g_agg[src] with vector RED (v4.f32).
// 4 threads per edge, each handling 4 consecutive float4 chunks (64B):
// MLP=4 loads, 1 index LDG per thread. g_agg (12.8MB) is L2-resident.
// ---------------------------------------------------------------------------
__global__ void k_scatter(const float* __restrict__ edge_attr,
                          const void* __restrict__ edge_index) {
    int t = blockIdx.x * blockDim.x + threadIdx.x;
    if (t >= N_EDGES * 4) return;
    int is64 = g_is64;
    int e = t >> 2;
    int q = t & 3;
    int src = load_index(edge_index, e, is64);
    if ((unsigned)src >= N_NODES) return;   // safety: never trap
    const float4* row = reinterpret_cast<const float4*>(edge_attr)
                        + (size_t)e * 16 + q * 4;
    float4 v0 = row[0];
    float4 v1 = row[1];
    float4 v2 = row[2];
    float4 v3 = row[3];
    float* base = &g_agg[src * D + q * 16];
    asm volatile("red.global.add.v4.f32 [%0], {%1,%2,%3,%4};"
                 :: "l"(base +  0), "f"(v0.x), "f"(v0.y), "f"(v0.z), "f"(v0.w) : "memory");
    asm volatile("red.global.add.v4.f32 [%0], {%1,%2,%3,%4};"
                 :: "l"(base +  4), "f"(v1.x), "f"(v1.y), "f"(v1.z), "f"(v1.w) : "memory");
    asm volatile("red.global.add.v4.f32 [%0], {%1,%2,%3,%4};"
                 :: "l"(base +  8), "f"(v2.x), "f"(v2.y), "f"(v2.z), "f"(v2.w) : "memory");
    asm volatile("red.global.add.v4.f32 [%0], {%1,%2,%3,%4};"
                 :: "l"(base + 12), "f"(v3.x), "f"(v3.y), "f"(v3.z), "f"(v3.w) : "memory");
    if (q == 0) {
        atomicAdd(&g_cnt[src], 1.0f);   // no return use -> REDG
    }
}

// ---------------------------------------------------------------------------
// k2: nemb = sigmoid((node_attr + agg*0.5/max(cnt,1)) @ W^T + b)
// Register-tiled GEMM, 4x4 tile/thread, float4 LDS operand reads.
// Stride 68 words: keeps 16B alignment for float4 LDS (68%4==0) while
// avoiding systematic bank alignment (68%32==4).
//   GEMM reads per k (per warp): xst float4 = 2 distinct 16B (broadcast),
//   wt float4 = 16 distinct 16B spanning 256B -> conflict-free.
// ---------------------------------------------------------------------------
#define S 68
__global__ void __launch_bounds__(256) k_node(const float* __restrict__ node_attr,
                                              const float* __restrict__ W,
                                              const float* __restrict__ b) {
    __shared__ float wt[64 * S];    // wt[k*S + j] = W[j*64 + k]
    __shared__ float xst[64 * S];   // xst[k*S + n] = x[node nb+n][k]
    __shared__ float bs[64];
    __shared__ float sinv[64];      // 0.5 / max(cnt, 1) per node

    const int tid = threadIdx.x;
    const int nb  = blockIdx.x * 64;          // first node of this block

    if (tid < 64) {
        bs[tid] = b[tid];
        int n_g = nb + tid;
        float cnt = (n_g < N_NODES) ? g_cnt[n_g] : 1.0f;
        sinv[tid] = 0.5f / fmaxf(cnt, 1.0f);
    }
    // W transpose fill: coalesced global read; STS 8-way conflicts but only
    // 16 iterations -> negligible vs the FMA mainloop.
    #pragma unroll
    for (int i = tid; i < 64 * 64; i += 256) {
        int j = i >> 6;
        int k = i & 63;
        wt[k * S + j] = W[i];
    }
    __syncthreads();   // sinv ready before x fill uses it

    // x fill (transposed): coalesced global reads.
    #pragma unroll
    for (int i = tid; i < 64 * 64; i += 256) {
        int n = i >> 6;
        int k = i & 63;
        int n_g = nb + n;
        float v = 0.0f;
        if (n_g < N_NODES) {
            v = node_attr[n_g * D + k] + g_agg[n_g * D + k] * sinv[n];
        }
        xst[k * S + n] = v;
    }
    __syncthreads();

    // --- 4x4 register-tiled GEMM with float4 operand loads ---
    const int jg = tid & 15;          // feature group (fast within warp)
    const int ng = tid >> 4;          // node group
    const int j0 = jg * 4;
    const int n0 = ng * 4;

    float acc[4][4];
    #pragma unroll
    for (int a = 0; a < 4; a++)
        #pragma unroll
        for (int c = 0; c < 4; c++)
            acc[a][c] = bs[j0 + c];

    #pragma unroll 8
    for (int k = 0; k < 64; k++) {
        float4 xv = *reinterpret_cast<const float4*>(&xst[k * S + n0]);
        float4 wv = *reinterpret_cast<const float4*>(&wt[k * S + j0]);
        acc[0][0] = fmaf(xv.x, wv.x, acc[0][0]); acc[0][1] = fmaf(xv.x, wv.y, acc[0][1]);
        acc[0][2] = fmaf(xv.x, wv.z, acc[0][2]); acc[0][3] = fmaf(xv.x, wv.w, acc[0][3]);
        acc[1][0] = fmaf(xv.y, wv.x, acc[1][0]); acc[1][1] = fmaf(xv.y, wv.y, acc[1][1]);
        acc[1][2] = fmaf(xv.y, wv.z, acc[1][2]); acc[1][3] = fmaf(xv.y, wv.w, acc[1][3]);
        acc[2][0] = fmaf(xv.z, wv.x, acc[2][0]); acc[2][1] = fmaf(xv.z, wv.y, acc[2][1]);
        acc[2][2] = fmaf(xv.z, wv.z, acc[2][2]); acc[2][3] = fmaf(xv.z, wv.w, acc[2][3]);
        acc[3][0] = fmaf(xv.w, wv.x, acc[3][0]); acc[3][1] = fmaf(xv.w, wv.y, acc[3][1]);
        acc[3][2] = fmaf(xv.w, wv.z, acc[3][2]); acc[3][3] = fmaf(xv.w, wv.w, acc[3][3]);
    }

    // sigmoid + vectorized store (contiguous 16B per thread, coalesced rows)
    #pragma unroll
    for (int a = 0; a < 4; a++) {
        int n_g = nb + n0 + a;
        if (n_g < N_NODES) {
            float4 o;
            o.x = 1.0f / (1.0f + __expf(-acc[a][0]));
            o.y = 1.0f / (1.0f + __expf(-acc[a][1]));
            o.z = 1.0f / (1.0f + __expf(-acc[a][2]));
            o.w = 1.0f / (1.0f + __expf(-acc[a][3]));
            *reinterpret_cast<float4*>(&g_nemb[n_g * D + j0]) = o;
        }
    }
}
#undef S

// ---------------------------------------------------------------------------
// k3: edge output: out[e] = (nemb[src] + nemb[dst]) * 0.5
// 4 threads per edge, 4 float4 chunks each: MLP=8 gathers (L2-resident nemb),
// 2 index LDGs per thread, 2KB contiguous stores per warp.
// ---------------------------------------------------------------------------
__global__ void k_edge(const void* __restrict__ edge_index,
                       float* __restrict__ out) {
    int t = blockIdx.x * blockDim.x + threadIdx.x;
    if (t >= N_EDGES * 4) return;
    int is64 = g_is64;
    int e = t >> 2;
    int q = t & 3;
    int src = load_index(edge_index, e, is64);
    int dst = load_index(edge_index, N_EDGES + e, is64);
    float4 a[4], d[4];
    #pragma unroll
    for (int i = 0; i < 4; i++) a[i] = make_float4(0.f, 0.f, 0.f, 0.f);
    #pragma unroll
    for (int i = 0; i < 4; i++) d[i] = make_float4(0.f, 0.f, 0.f, 0.f);
    if ((unsigned)src < N_NODES) {
        const float4* pa = reinterpret_cast<const float4*>(g_nemb) + (size_t)src * 16 + q * 4;
        #pragma unroll
        for (int i = 0; i < 4; i++) a[i] = pa[i];
    }
    if ((unsigned)dst < N_NODES) {
        const float4* pd = reinterpret_cast<const float4*>(g_nemb) + (size_t)dst * 16 + q * 4;
        #pragma unroll
        for (int i = 0; i < 4; i++) d[i] = pd[i];
    }
    float4* po = reinterpret_cast<float4*>(out) + (size_t)e * 16 + q * 4;
    #pragma unroll
    for (int i = 0; i < 4; i++) {
        float4 o = make_float4((a[i].x + d[i].x) * 0.5f,
                               (a[i].y + d[i].y) * 0.5f,
                               (a[i].z + d[i].z) * 0.5f,
                               (a[i].w + d[i].w) * 0.5f);
        po[i] = o;
    }
}

// ---------------------------------------------------------------------------
// Inputs identified BY ELEMENT COUNT (robust to metadata ordering):
//   edge_attr  f32     [800000,64] -> 51,200,000
//   edge_index i32/i64 [2,800000]  ->  1,600,000
//   node_attr  f32     [50000,64]  ->  3,200,000
//   W          f32     [64,64]     ->      4,096
//   b          f32     [64]        ->         64
// Output: f32 [800000,64]
// ---------------------------------------------------------------------------
extern "C" void kernel_launch(void* const* d_in, const int* in_sizes, int n_in,
                              void* d_out, int out_size) {
    const float* edge_attr  = nullptr;
    const void*  edge_index = nullptr;
    const float* node_attr  = nullptr;
    const float* W          = nullptr;
    const float* b          = nullptr;

    int c32[4]; int n32 = 0;
    for (int i = 0; i < n_in; i++) {
        switch (in_sizes[i]) {
            case 51200000: edge_attr  = (const float*)d_in[i]; break;
            case 1600000:  edge_index = d_in[i];               break;
            case 3200000:  if (n32 < 4) c32[n32++] = i;        break;
            case 4096:     W          = (const float*)d_in[i]; break;
            case 64:       b          = (const float*)d_in[i]; break;
            default: break;
        }
    }
    if (n32 == 1) {
        node_attr = (const float*)d_in[c32[0]];
    } else if (n32 >= 2) {
        if (!edge_index) { edge_index = d_in[c32[0]]; node_attr = (const float*)d_in[c32[1]]; }
        else             { node_attr  = (const float*)d_in[c32[0]]; }
    }
    float* out = (float*)d_out;

    const int ZERO4 = (N_NODES * D) / 4 + N_NODES / 4;   // 812500
    k_zero<<<(ZERO4 + 255) / 256, 256>>>((const int2*)edge_index);

    const int EV = N_EDGES * 4;                           // 3.2M
    k_scatter<<<(EV + 255) / 256, 256>>>(edge_attr, edge_index);

    k_node<<<(N_NODES + 63) / 64, 256>>>(node_attr, W, b);

    k_edge<<<(EV + 255) / 256, 256>>>(edge_index, out);
}

// round 11
// speedup vs baseline: 1.2537x; 1.2537x over previous
#include <cuda_runtime.h>
#include <cuda_fp16.h>
#include <cuda_bf16.h>

#define N_NODES 50000
#define N_EDGES 800000
#define D 64

// Scratch (no allocations allowed): static device globals.
// __align__(16): red.global.add.v4.f32 / float4 ld+st require 16B alignment.
__device__ __align__(16) float  g_agg[N_NODES * D];   // scatter-sum of edge_attr
__device__ __align__(16) float  g_cnt[N_NODES];       // per-src edge counts
__device__ __align__(16) __half g_nemb[N_NODES * D];  // fp16 node embeddings (row = 128B)
__device__ int g_is64;                                // 1 = edge_index is int64

__device__ __forceinline__ int load_index(const void* ei, int pos, int is64) {
    if (is64) return (int)((const long long*)ei)[pos];
    return ((const int*)ei)[pos];
}

// ---------------------------------------------------------------------------
// k0: zero agg + cnt with float4 stores; block 0 also runs the int32/int64
// detection (int64 indices < 50000 -> all high words zero).
// ---------------------------------------------------------------------------
__global__ void k_zero(const int2* __restrict__ ei) {
    if (blockIdx.x == 0) {
        int local = 0;
        for (int i = threadIdx.x; i < 4096; i += blockDim.x)
            local |= ei[i].y;
        __shared__ int any_hi;
        if (threadIdx.x == 0) any_hi = 0;
        __syncthreads();
        local |= __shfl_xor_sync(0xffffffffu, local, 16);
        local |= __shfl_xor_sync(0xffffffffu, local, 8);
        local |= __shfl_xor_sync(0xffffffffu, local, 4);
        local |= __shfl_xor_sync(0xffffffffu, local, 2);
        local |= __shfl_xor_sync(0xffffffffu, local, 1);
        if ((threadIdx.x & 31) == 0 && local) any_hi = 1;
        __syncthreads();
        if (threadIdx.x == 0) g_is64 = (any_hi == 0) ? 1 : 0;
    }
    int i = blockIdx.x * blockDim.x + threadIdx.x;
    const int AGG4 = (N_NODES * D) / 4;   // 800000
    const int CNT4 = N_NODES / 4;         // 12500
    float4 z = make_float4(0.f, 0.f, 0.f, 0.f);
    if (i < AGG4) {
        reinterpret_cast<float4*>(g_agg)[i] = z;
    } else if (i < AGG4 + CNT4) {
        reinterpret_cast<float4*>(g_cnt)[i - AGG4] = z;
    }
}

// ---------------------------------------------------------------------------
// k1: scatter-add edge_attr rows onto g_agg[src] with vector RED (v4.f32).
// R9 layout (proven fast): 16 threads per edge, one float4 + one red.v4 each.
// Warp = 2 edges; lanes read CONSECUTIVE float4s of a row -> dense lines.
// g_agg (12.8MB) is L2-resident -> atomics serviced on-die.
// ---------------------------------------------------------------------------
__global__ void k_scatter(const float* __restrict__ edge_attr,
                          const void* __restrict__ edge_index) {
    int idx = blockIdx.x * blockDim.x + threadIdx.x;
    if (idx >= N_EDGES * 16) return;
    int is64 = g_is64;
    int e = idx >> 4;
    int c = idx & 15;
    int src = load_index(edge_index, e, is64);
    if ((unsigned)src >= N_NODES) return;   // safety: never trap
    float4 v = reinterpret_cast<const float4*>(edge_attr)[(size_t)e * 16 + c];
    float* p = &g_agg[src * D + c * 4];
    asm volatile("red.global.add.v4.f32 [%0], {%1,%2,%3,%4};"
                 :: "l"(p), "f"(v.x), "f"(v.y), "f"(v.z), "f"(v.w)
                 : "memory");
    if (c == 0) {
        atomicAdd(&g_cnt[src], 1.0f);   // no return use -> REDG
    }
}

// ---------------------------------------------------------------------------
// k2: nemb = sigmoid((node_attr + agg*0.5/max(cnt,1)) @ W^T + b), stored fp16.
// Register-tiled GEMM, 4x4 tile/thread, float4 LDS operand reads.
// Stride 68 words: 16B alignment for float4 LDS (68%4==0), 68%32!=0 avoids
// systematic bank alignment.
// ---------------------------------------------------------------------------
#define S 68
__global__ void __launch_bounds__(256) k_node(const float* __restrict__ node_attr,
                                              const float* __restrict__ W,
                                              const float* __restrict__ b) {
    __shared__ float wt[64 * S];    // wt[k*S + j] = W[j*64 + k]
    __shared__ float xst[64 * S];   // xst[k*S + n] = x[node nb+n][k]
    __shared__ float bs[64];
    __shared__ float sinv[64];      // 0.5 / max(cnt, 1) per node

    const int tid = threadIdx.x;
    const int nb  = blockIdx.x * 64;          // first node of this block

    if (tid < 64) {
        bs[tid] = b[tid];
        int n_g = nb + tid;
        float cnt = (n_g < N_NODES) ? g_cnt[n_g] : 1.0f;
        sinv[tid] = 0.5f / fmaxf(cnt, 1.0f);
    }
    // W transpose fill: coalesced global read.
    #pragma unroll
    for (int i = tid; i < 64 * 64; i += 256) {
        int j = i >> 6;
        int k = i & 63;
        wt[k * S + j] = W[i];
    }
    __syncthreads();   // sinv ready before x fill uses it

    // x fill (transposed): coalesced global reads.
    #pragma unroll
    for (int i = tid; i < 64 * 64; i += 256) {
        int n = i >> 6;
        int k = i & 63;
        int n_g = nb + n;
        float v = 0.0f;
        if (n_g < N_NODES) {
            v = node_attr[n_g * D + k] + g_agg[n_g * D + k] * sinv[n];
        }
        xst[k * S + n] = v;
    }
    __syncthreads();

    // --- 4x4 register-tiled GEMM with float4 operand loads ---
    const int jg = tid & 15;          // feature group
    const int ng = tid >> 4;          // node group
    const int j0 = jg * 4;
    const int n0 = ng * 4;

    float acc[4][4];
    #pragma unroll
    for (int a = 0; a < 4; a++)
        #pragma unroll
        for (int c = 0; c < 4; c++)
            acc[a][c] = bs[j0 + c];

    #pragma unroll 8
    for (int k = 0; k < 64; k++) {
        float4 xv = *reinterpret_cast<const float4*>(&xst[k * S + n0]);
        float4 wv = *reinterpret_cast<const float4*>(&wt[k * S + j0]);
        acc[0][0] = fmaf(xv.x, wv.x, acc[0][0]); acc[0][1] = fmaf(xv.x, wv.y, acc[0][1]);
        acc[0][2] = fmaf(xv.x, wv.z, acc[0][2]); acc[0][3] = fmaf(xv.x, wv.w, acc[0][3]);
        acc[1][0] = fmaf(xv.y, wv.x, acc[1][0]); acc[1][1] = fmaf(xv.y, wv.y, acc[1][1]);
        acc[1][2] = fmaf(xv.y, wv.z, acc[1][2]); acc[1][3] = fmaf(xv.y, wv.w, acc[1][3]);
        acc[2][0] = fmaf(xv.z, wv.x, acc[2][0]); acc[2][1] = fmaf(xv.z, wv.y, acc[2][1]);
        acc[2][2] = fmaf(xv.z, wv.z, acc[2][2]); acc[2][3] = fmaf(xv.z, wv.w, acc[2][3]);
        acc[3][0] = fmaf(xv.w, wv.x, acc[3][0]); acc[3][1] = fmaf(xv.w, wv.y, acc[3][1]);
        acc[3][2] = fmaf(xv.w, wv.z, acc[3][2]); acc[3][3] = fmaf(xv.w, wv.w, acc[3][3]);
    }

    // sigmoid -> fp16 pack -> 8B store per node row segment
    #pragma unroll
    for (int a = 0; a < 4; a++) {
        int n_g = nb + n0 + a;
        if (n_g < N_NODES) {
            float s0 = 1.0f / (1.0f + __expf(-acc[a][0]));
            float s1 = 1.0f / (1.0f + __expf(-acc[a][1]));
            float s2 = 1.0f / (1.0f + __expf(-acc[a][2]));
            float s3 = 1.0f / (1.0f + __expf(-acc[a][3]));
            __half2 h0 = __floats2half2_rn(s0, s1);
            __half2 h1 = __floats2half2_rn(s2, s3);
            uint2 pk;
            pk.x = *reinterpret_cast<unsigned int*>(&h0);
            pk.y = *reinterpret_cast<unsigned int*>(&h1);
            *reinterpret_cast<uint2*>(&g_nemb[n_g * D + j0]) = pk;
        }
    }
}
#undef S

// ---------------------------------------------------------------------------
// k3: edge output: out[e] = (nemb[src] + nemb[dst]) * 0.5
// 8 threads per edge; each loads 16B (8 fp16) per node -> a node row is ONE
// 128B line, gather LDGs are lane-consecutive (4 dense lines per warp).
// Each thread writes 32B of out; warp stores 4 contiguous 256B rows.
// ---------------------------------------------------------------------------
__global__ void k_edge(const void* __restrict__ edge_index,
                       float* __restrict__ out) {
    int t = blockIdx.x * blockDim.x + threadIdx.x;
    if (t >= N_EDGES * 8) return;
    int is64 = g_is64;
    int e = t >> 3;
    int c = t & 7;
    int src = load_index(edge_index, e, is64);
    int dst = load_index(edge_index, N_EDGES + e, is64);
    uint4 ha = make_uint4(0u, 0u, 0u, 0u);
    uint4 hd = make_uint4(0u, 0u, 0u, 0u);
    if ((unsigned)src < N_NODES)
        ha = reinterpret_cast<const uint4*>(g_nemb)[(size_t)src * 8 + c];
    if ((unsigned)dst < N_NODES)
        hd = reinterpret_cast<const uint4*>(g_nemb)[(size_t)dst * 8 + c];

    const __half2* pa = reinterpret_cast<const __half2*>(&ha);
    const __half2* pd = reinterpret_cast<const __half2*>(&hd);
    float4 o0, o1;
    {
        float2 a0 = __half22float2(pa[0]); float2 d0 = __half22float2(pd[0]);
        float2 a1 = __half22float2(pa[1]); float2 d1 = __half22float2(pd[1]);
        o0 = make_float4((a0.x + d0.x) * 0.5f, (a0.y + d0.y) * 0.5f,
                         (a1.x + d1.x) * 0.5f, (a1.y + d1.y) * 0.5f);
        float2 a2 = __half22float2(pa[2]); float2 d2 = __half22float2(pd[2]);
        float2 a3 = __half22float2(pa[3]); float2 d3 = __half22float2(pd[3]);
        o1 = make_float4((a2.x + d2.x) * 0.5f, (a2.y + d2.y) * 0.5f,
                         (a3.x + d3.x) * 0.5f, (a3.y + d3.y) * 0.5f);
    }
    float4* po = reinterpret_cast<float4*>(out) + (size_t)e * 16 + c * 2;
    po[0] = o0;
    po[1] = o1;
}

// ---------------------------------------------------------------------------
// Inputs identified BY ELEMENT COUNT (robust to metadata ordering):
//   edge_attr  f32     [800000,64] -> 51,200,000
//   edge_index i32/i64 [2,800000]  ->  1,600,000
//   node_attr  f32     [50000,64]  ->  3,200,000
//   W          f32     [64,64]     ->      4,096
//   b          f32     [64]        ->         64
// Output: f32 [800000,64]
// ---------------------------------------------------------------------------
extern "C" void kernel_launch(void* const* d_in, const int* in_sizes, int n_in,
                              void* d_out, int out_size) {
    const float* edge_attr  = nullptr;
    const void*  edge_index = nullptr;
    const float* node_attr  = nullptr;
    const float* W          = nullptr;
    const float* b          = nullptr;

    int c32[4]; int n32 = 0;
    for (int i = 0; i < n_in; i++) {
        switch (in_sizes[i]) {
            case 51200000: edge_attr  = (const float*)d_in[i]; break;
            case 1600000:  edge_index = d_in[i];               break;
            case 3200000:  if (n32 < 4) c32[n32++] = i;        break;
            case 4096:     W          = (const float*)d_in[i]; break;
            case 64:       b          = (const float*)d_in[i]; break;
            default: break;
        }
    }
    if (n32 == 1) {
        node_attr = (const float*)d_in[c32[0]];
    } else if (n32 >= 2) {
        if (!edge_index) { edge_index = d_in[c32[0]]; node_attr = (const float*)d_in[c32[1]]; }
        else             { node_attr  = (const float*)d_in[c32[0]]; }
    }
    float* out = (float*)d_out;

    const int ZERO4 = (N_NODES * D) / 4 + N_NODES / 4;   // 812500
    k_zero<<<(ZERO4 + 255) / 256, 256>>>((const int2*)edge_index);

    const int SCAT = N_EDGES * 16;                        // 12.8M
    k_scatter<<<(SCAT + 255) / 256, 256>>>(edge_attr, edge_index);

    k_node<<<(N_NODES + 63) / 64, 256>>>(node_attr, W, b);

    const int EDG = N_EDGES * 8;                          // 6.4M
    k_edge<<<(EDG + 255) / 256, 256>>>(edge_index, out);
}

// round 12
// speedup vs baseline: 1.3723x; 1.0946x over previous
#include <cuda_runtime.h>
#include <cuda_fp16.h>
#include <cuda_bf16.h>

#define N_NODES 50000
#define N_EDGES 800000
#define D 64

// Scratch (no allocations allowed): static device globals.
// __align__(16): red.global.add.v4.f32 / float4 ld+st require 16B alignment.
__device__ __align__(16) float  g_agg[N_NODES * D];   // scatter-sum of edge_attr
__device__ __align__(16) float  g_cnt[N_NODES];       // per-src edge counts
__device__ __align__(16) __half g_nemb[N_NODES * D];  // fp16 node embeddings (row = 128B)
__device__ int g_is64;                                // 1 = edge_index is int64

__device__ __forceinline__ int load_index(const void* ei, int pos, int is64) {
    if (is64) return (int)((const long long*)ei)[pos];
    return ((const int*)ei)[pos];
}

// ---------------------------------------------------------------------------
// k0: zero agg + cnt with float4 stores; block 0 also runs the int32/int64
// detection (int64 indices < 50000 -> all high words zero).
// ---------------------------------------------------------------------------
__global__ void k_zero(const int2* __restrict__ ei) {
    if (blockIdx.x == 0) {
        int local = 0;
        for (int i = threadIdx.x; i < 4096; i += blockDim.x)
            local |= ei[i].y;
        __shared__ int any_hi;
        if (threadIdx.x == 0) any_hi = 0;
        __syncthreads();
        local |= __shfl_xor_sync(0xffffffffu, local, 16);
        local |= __shfl_xor_sync(0xffffffffu, local, 8);
        local |= __shfl_xor_sync(0xffffffffu, local, 4);
        local |= __shfl_xor_sync(0xffffffffu, local, 2);
        local |= __shfl_xor_sync(0xffffffffu, local, 1);
        if ((threadIdx.x & 31) == 0 && local) any_hi = 1;
        __syncthreads();
        if (threadIdx.x == 0) g_is64 = (any_hi == 0) ? 1 : 0;
    }
    int i = blockIdx.x * blockDim.x + threadIdx.x;
    const int AGG4 = (N_NODES * D) / 4;   // 800000
    const int CNT4 = N_NODES / 4;         // 12500
    float4 z = make_float4(0.f, 0.f, 0.f, 0.f);
    if (i < AGG4) {
        reinterpret_cast<float4*>(g_agg)[i] = z;
    } else if (i < AGG4 + CNT4) {
        reinterpret_cast<float4*>(g_cnt)[i - AGG4] = z;
    }
}

// ---------------------------------------------------------------------------
// k1: scatter-add edge_attr rows onto g_agg[src] with vector RED (v4.f32).
// 16 threads per edge, one float4 + one red.v4 each; lanes read CONSECUTIVE
// float4s of a row -> dense lines. edge_attr is read ONCE -> __ldcs streaming
// (evict-first) so the 205MB stream doesn't evict L2-resident g_agg.
// ---------------------------------------------------------------------------
__global__ void k_scatter(const float* __restrict__ edge_attr,
                          const void* __restrict__ edge_index) {
    int idx = blockIdx.x * blockDim.x + threadIdx.x;
    if (idx >= N_EDGES * 16) return;
    int is64 = g_is64;
    int e = idx >> 4;
    int c = idx & 15;
    int src = load_index(edge_index, e, is64);
    if ((unsigned)src >= N_NODES) return;   // safety: never trap
    float4 v = __ldcs(reinterpret_cast<const float4*>(edge_attr) + (size_t)e * 16 + c);
    float* p = &g_agg[src * D + c * 4];
    asm volatile("red.global.add.v4.f32 [%0], {%1,%2,%3,%4};"
                 :: "l"(p), "f"(v.x), "f"(v.y), "f"(v.z), "f"(v.w)
                 : "memory");
    if (c == 0) {
        atomicAdd(&g_cnt[src], 1.0f);   // no return use -> REDG
    }
}

// ---------------------------------------------------------------------------
// k2: nemb = sigmoid((node_attr + agg*0.5/max(cnt,1)) @ W^T + b), stored fp16.
// Register-tiled GEMM, 4x4 tile/thread, float4 LDS operand reads.
// Stride 68 words: 16B alignment for float4 LDS (68%4==0), 68%32!=0 avoids
// systematic bank alignment.
// ---------------------------------------------------------------------------
#define S 68
__global__ void __launch_bounds__(256) k_node(const float* __restrict__ node_attr,
                                              const float* __restrict__ W,
                                              const float* __restrict__ b) {
    __shared__ float wt[64 * S];    // wt[k*S + j] = W[j*64 + k]
    __shared__ float xst[64 * S];   // xst[k*S + n] = x[node nb+n][k]
    __shared__ float bs[64];
    __shared__ float sinv[64];      // 0.5 / max(cnt, 1) per node

    const int tid = threadIdx.x;
    const int nb  = blockIdx.x * 64;          // first node of this block

    if (tid < 64) {
        bs[tid] = b[tid];
        int n_g = nb + tid;
        float cnt = (n_g < N_NODES) ? g_cnt[n_g] : 1.0f;
        sinv[tid] = 0.5f / fmaxf(cnt, 1.0f);
    }
    // W transpose fill: coalesced global read.
    #pragma unroll
    for (int i = tid; i < 64 * 64; i += 256) {
        int j = i >> 6;
        int k = i & 63;
        wt[k * S + j] = W[i];
    }
    __syncthreads();   // sinv ready before x fill uses it

    // x fill (transposed): coalesced global reads.
    #pragma unroll
    for (int i = tid; i < 64 * 64; i += 256) {
        int n = i >> 6;
        int k = i & 63;
        int n_g = nb + n;
        float v = 0.0f;
        if (n_g < N_NODES) {
            v = node_attr[n_g * D + k] + g_agg[n_g * D + k] * sinv[n];
        }
        xst[k * S + n] = v;
    }
    __syncthreads();

    // --- 4x4 register-tiled GEMM with float4 operand loads ---
    const int jg = tid & 15;          // feature group
    const int ng = tid >> 4;          // node group
    const int j0 = jg * 4;
    const int n0 = ng * 4;

    float acc[4][4];
    #pragma unroll
    for (int a = 0; a < 4; a++)
        #pragma unroll
        for (int c = 0; c < 4; c++)
            acc[a][c] = bs[j0 + c];

    #pragma unroll 8
    for (int k = 0; k < 64; k++) {
        float4 xv = *reinterpret_cast<const float4*>(&xst[k * S + n0]);
        float4 wv = *reinterpret_cast<const float4*>(&wt[k * S + j0]);
        acc[0][0] = fmaf(xv.x, wv.x, acc[0][0]); acc[0][1] = fmaf(xv.x, wv.y, acc[0][1]);
        acc[0][2] = fmaf(xv.x, wv.z, acc[0][2]); acc[0][3] = fmaf(xv.x, wv.w, acc[0][3]);
        acc[1][0] = fmaf(xv.y, wv.x, acc[1][0]); acc[1][1] = fmaf(xv.y, wv.y, acc[1][1]);
        acc[1][2] = fmaf(xv.y, wv.z, acc[1][2]); acc[1][3] = fmaf(xv.y, wv.w, acc[1][3]);
        acc[2][0] = fmaf(xv.z, wv.x, acc[2][0]); acc[2][1] = fmaf(xv.z, wv.y, acc[2][1]);
        acc[2][2] = fmaf(xv.z, wv.z, acc[2][2]); acc[2][3] = fmaf(xv.z, wv.w, acc[2][3]);
        acc[3][0] = fmaf(xv.w, wv.x, acc[3][0]); acc[3][1] = fmaf(xv.w, wv.y, acc[3][1]);
        acc[3][2] = fmaf(xv.w, wv.z, acc[3][2]); acc[3][3] = fmaf(xv.w, wv.w, acc[3][3]);
    }

    // sigmoid -> fp16 pack -> 8B store per node row segment
    #pragma unroll
    for (int a = 0; a < 4; a++) {
        int n_g = nb + n0 + a;
        if (n_g < N_NODES) {
            float s0 = 1.0f / (1.0f + __expf(-acc[a][0]));
            float s1 = 1.0f / (1.0f + __expf(-acc[a][1]));
            float s2 = 1.0f / (1.0f + __expf(-acc[a][2]));
            float s3 = 1.0f / (1.0f + __expf(-acc[a][3]));
            __half2 h0 = __floats2half2_rn(s0, s1);
            __half2 h1 = __floats2half2_rn(s2, s3);
            uint2 pk;
            pk.x = *reinterpret_cast<unsigned int*>(&h0);
            pk.y = *reinterpret_cast<unsigned int*>(&h1);
            *reinterpret_cast<uint2*>(&g_nemb[n_g * D + j0]) = pk;
        }
    }
}
#undef S

// ---------------------------------------------------------------------------
// k3: edge output: out[e] = (nemb[src] + nemb[dst]) * 0.5
// 8 threads per edge slot, TWO edges per thread (e and e+400000): every
// LDG/STG keeps R11's dense lane-consecutive layout, but per-thread MLP
// doubles (4 gathers + 4 stores in flight). Out stores use __stcs
// (streaming) so the 205MB write stream doesn't evict L2-resident g_nemb.
// ---------------------------------------------------------------------------
__device__ __forceinline__ void edge_avg(uint4 ha, uint4 hd, float4& o0, float4& o1) {
    const __half2* pa = reinterpret_cast<const __half2*>(&ha);
    const __half2* pd = reinterpret_cast<const __half2*>(&hd);
    float2 a0 = __half22float2(pa[0]); float2 d0 = __half22float2(pd[0]);
    float2 a1 = __half22float2(pa[1]); float2 d1 = __half22float2(pd[1]);
    o0 = make_float4((a0.x + d0.x) * 0.5f, (a0.y + d0.y) * 0.5f,
                     (a1.x + d1.x) * 0.5f, (a1.y + d1.y) * 0.5f);
    float2 a2 = __half22float2(pa[2]); float2 d2 = __half22float2(pd[2]);
    float2 a3 = __half22float2(pa[3]); float2 d3 = __half22float2(pd[3]);
    o1 = make_float4((a2.x + d2.x) * 0.5f, (a2.y + d2.y) * 0.5f,
                     (a3.x + d3.x) * 0.5f, (a3.y + d3.y) * 0.5f);
}

__global__ void k_edge(const void* __restrict__ edge_index,
                       float* __restrict__ out) {
    const int HALF = N_EDGES / 2;   // 400000
    int t = blockIdx.x * blockDim.x + threadIdx.x;
    if (t >= HALF * 8) return;
    int is64 = g_is64;
    int e0 = t >> 3;
    int c  = t & 7;
    int e1 = e0 + HALF;

    int s0 = load_index(edge_index, e0, is64);
    int d0 = load_index(edge_index, N_EDGES + e0, is64);
    int s1 = load_index(edge_index, e1, is64);
    int d1 = load_index(edge_index, N_EDGES + e1, is64);

    uint4 zero = make_uint4(0u, 0u, 0u, 0u);
    uint4 ha0 = zero, hd0 = zero, ha1 = zero, hd1 = zero;
    const uint4* nb = reinterpret_cast<const uint4*>(g_nemb);
    // 4 independent gathers -> MLP=4 before any consumption
    if ((unsigned)s0 < N_NODES) ha0 = nb[(size_t)s0 * 8 + c];
    if ((unsigned)d0 < N_NODES) hd0 = nb[(size_t)d0 * 8 + c];
    if ((unsigned)s1 < N_NODES) ha1 = nb[(size_t)s1 * 8 + c];
    if ((unsigned)d1 < N_NODES) hd1 = nb[(size_t)d1 * 8 + c];

    float4 o0, o1;
    edge_avg(ha0, hd0, o0, o1);
    float4* po0 = reinterpret_cast<float4*>(out) + (size_t)e0 * 16 + c * 2;
    __stcs(po0 + 0, o0);
    __stcs(po0 + 1, o1);

    edge_avg(ha1, hd1, o0, o1);
    float4* po1 = reinterpret_cast<float4*>(out) + (size_t)e1 * 16 + c * 2;
    __stcs(po1 + 0, o0);
    __stcs(po1 + 1, o1);
}

// ---------------------------------------------------------------------------
// Inputs identified BY ELEMENT COUNT (robust to metadata ordering):
//   edge_attr  f32     [800000,64] -> 51,200,000
//   edge_index i32/i64 [2,800000]  ->  1,600,000
//   node_attr  f32     [50000,64]  ->  3,200,000
//   W          f32     [64,64]     ->      4,096
//   b          f32     [64]        ->         64
// Output: f32 [800000,64]
// ---------------------------------------------------------------------------
extern "C" void kernel_launch(void* const* d_in, const int* in_sizes, int n_in,
                              void* d_out, int out_size) {
    const float* edge_attr  = nullptr;
    const void*  edge_index = nullptr;
    const float* node_attr  = nullptr;
    const float* W          = nullptr;
    const float* b          = nullptr;

    int c32[4]; int n32 = 0;
    for (int i = 0; i < n_in; i++) {
        switch (in_sizes[i]) {
            case 51200000: edge_attr  = (const float*)d_in[i]; break;
            case 1600000:  edge_index = d_in[i];               break;
            case 3200000:  if (n32 < 4) c32[n32++] = i;        break;
            case 4096:     W          = (const float*)d_in[i]; break;
            case 64:       b          = (const float*)d_in[i]; break;
            default: break;
        }
    }
    if (n32 == 1) {
        node_attr = (const float*)d_in[c32[0]];
    } else if (n32 >= 2) {
        if (!edge_index) { edge_index = d_in[c32[0]]; node_attr = (const float*)d_in[c32[1]]; }
        else             { node_attr  = (const float*)d_in[c32[0]]; }
    }
    float* out = (float*)d_out;

    const int ZERO4 = (N_NODES * D) / 4 + N_NODES / 4;   // 812500
    k_zero<<<(ZERO4 + 255) / 256, 256>>>((const int2*)edge_index);

    const int SCAT = N_EDGES * 16;                        // 12.8M
    k_scatter<<<(SCAT + 255) / 256, 256>>>(edge_attr, edge_index);

    k_node<<<(N_NODES + 63) / 64, 256>>>(node_attr, W, b);

    const int EDG = (N_EDGES / 2) * 8;                    // 3.2M
    k_edge<<<(EDG + 255) / 256, 256>>>(edge_index, out);
}

// round 13
// speedup vs baseline: 1.4442x; 1.0524x over previous
#include <cuda_runtime.h>
#include <cuda_fp16.h>
#include <cuda_bf16.h>

#define N_NODES 50000
#define N_EDGES 800000
#define D 64

// Scratch (no allocations allowed): static device globals.
// __align__(16): red.global.add.v4.f32 / float4 ld+st require 16B alignment.
__device__ __align__(16) float  g_agg[N_NODES * D];   // scatter-sum of edge_attr
__device__ __align__(16) float  g_cnt[N_NODES];       // per-src edge counts
__device__ __align__(16) __half g_nemb[N_NODES * D];  // fp16 node embeddings (row = 128B)
__device__ int g_is64;                                // 1 = edge_index is int64

__device__ __forceinline__ int load_index(const void* ei, int pos, int is64) {
    if (is64) return (int)((const long long*)ei)[pos];
    return ((const int*)ei)[pos];
}

// ---------------------------------------------------------------------------
// k0: zero agg + cnt with float4 stores; block 0 also runs the int32/int64
// detection (int64 indices < 50000 -> all high words zero).
// ---------------------------------------------------------------------------
__global__ void k_zero(const int2* __restrict__ ei) {
    if (blockIdx.x == 0) {
        int local = 0;
        for (int i = threadIdx.x; i < 4096; i += blockDim.x)
            local |= ei[i].y;
        __shared__ int any_hi;
        if (threadIdx.x == 0) any_hi = 0;
        __syncthreads();
        local |= __shfl_xor_sync(0xffffffffu, local, 16);
        local |= __shfl_xor_sync(0xffffffffu, local, 8);
        local |= __shfl_xor_sync(0xffffffffu, local, 4);
        local |= __shfl_xor_sync(0xffffffffu, local, 2);
        local |= __shfl_xor_sync(0xffffffffu, local, 1);
        if ((threadIdx.x & 31) == 0 && local) any_hi = 1;
        __syncthreads();
        if (threadIdx.x == 0) g_is64 = (any_hi == 0) ? 1 : 0;
    }
    int i = blockIdx.x * blockDim.x + threadIdx.x;
    const int AGG4 = (N_NODES * D) / 4;   // 800000
    const int CNT4 = N_NODES / 4;         // 12500
    float4 z = make_float4(0.f, 0.f, 0.f, 0.f);
    if (i < AGG4) {
        reinterpret_cast<float4*>(g_agg)[i] = z;
    } else if (i < AGG4 + CNT4) {
        reinterpret_cast<float4*>(g_cnt)[i - AGG4] = z;
    }
}

// ---------------------------------------------------------------------------
// k1: scatter-add edge_attr rows onto g_agg[src] with vector RED (v4.f32).
// 16 lanes per edge (dense row reads), TWO edges per thread (e, e+400000):
// data-load MLP=2, index instructions halved. edge_attr read once -> __ldcs
// streaming so the 205MB stream doesn't evict L2-resident g_agg.
// ---------------------------------------------------------------------------
__global__ void k_scatter(const float* __restrict__ edge_attr,
                          const void* __restrict__ edge_index) {
    const int HALF = N_EDGES / 2;   // 400000
    int t = blockIdx.x * blockDim.x + threadIdx.x;
    if (t >= HALF * 16) return;
    int is64 = g_is64;
    int e0 = t >> 4;
    int c  = t & 15;
    int e1 = e0 + HALF;

    int s0 = load_index(edge_index, e0, is64);
    int s1 = load_index(edge_index, e1, is64);

    // two independent streaming loads in flight before any RED
    float4 v0 = __ldcs(reinterpret_cast<const float4*>(edge_attr) + (size_t)e0 * 16 + c);
    float4 v1 = __ldcs(reinterpret_cast<const float4*>(edge_attr) + (size_t)e1 * 16 + c);

    if ((unsigned)s0 < N_NODES) {
        float* p = &g_agg[s0 * D + c * 4];
        asm volatile("red.global.add.v4.f32 [%0], {%1,%2,%3,%4};"
                     :: "l"(p), "f"(v0.x), "f"(v0.y), "f"(v0.z), "f"(v0.w) : "memory");
        if (c == 0) atomicAdd(&g_cnt[s0], 1.0f);
    }
    if ((unsigned)s1 < N_NODES) {
        float* p = &g_agg[s1 * D + c * 4];
        asm volatile("red.global.add.v4.f32 [%0], {%1,%2,%3,%4};"
                     :: "l"(p), "f"(v1.x), "f"(v1.y), "f"(v1.z), "f"(v1.w) : "memory");
        if (c == 0) atomicAdd(&g_cnt[s1], 1.0f);
    }
}

// ---------------------------------------------------------------------------
// k2: nemb = sigmoid((node_attr + agg*0.5/max(cnt,1)) @ W^T + b), stored fp16.
// Register-tiled GEMM, 4x4 tile/thread, float4 LDS operand reads.
// Stride 68 words: 16B alignment for float4 LDS (68%4==0), 68%32!=0 avoids
// systematic bank alignment.
// ---------------------------------------------------------------------------
#define S 68
__global__ void __launch_bounds__(256) k_node(const float* __restrict__ node_attr,
                                              const float* __restrict__ W,
                                              const float* __restrict__ b) {
    __shared__ float wt[64 * S];    // wt[k*S + j] = W[j*64 + k]
    __shared__ float xst[64 * S];   // xst[k*S + n] = x[node nb+n][k]
    __shared__ float bs[64];
    __shared__ float sinv[64];      // 0.5 / max(cnt, 1) per node

    const int tid = threadIdx.x;
    const int nb  = blockIdx.x * 64;          // first node of this block

    if (tid < 64) {
        bs[tid] = b[tid];
        int n_g = nb + tid;
        float cnt = (n_g < N_NODES) ? g_cnt[n_g] : 1.0f;
        sinv[tid] = 0.5f / fmaxf(cnt, 1.0f);
    }
    // W transpose fill: coalesced global read.
    #pragma unroll
    for (int i = tid; i < 64 * 64; i += 256) {
        int j = i >> 6;
        int k = i & 63;
        wt[k * S + j] = W[i];
    }
    __syncthreads();   // sinv ready before x fill uses it

    // x fill (transposed): coalesced global reads.
    #pragma unroll
    for (int i = tid; i < 64 * 64; i += 256) {
        int n = i >> 6;
        int k = i & 63;
        int n_g = nb + n;
        float v = 0.0f;
        if (n_g < N_NODES) {
            v = node_attr[n_g * D + k] + g_agg[n_g * D + k] * sinv[n];
        }
        xst[k * S + n] = v;
    }
    __syncthreads();

    // --- 4x4 register-tiled GEMM with float4 operand loads ---
    const int jg = tid & 15;          // feature group
    const int ng = tid >> 4;          // node group
    const int j0 = jg * 4;
    const int n0 = ng * 4;

    float acc[4][4];
    #pragma unroll
    for (int a = 0; a < 4; a++)
        #pragma unroll
        for (int c = 0; c < 4; c++)
            acc[a][c] = bs[j0 + c];

    #pragma unroll 8
    for (int k = 0; k < 64; k++) {
        float4 xv = *reinterpret_cast<const float4*>(&xst[k * S + n0]);
        float4 wv = *reinterpret_cast<const float4*>(&wt[k * S + j0]);
        acc[0][0] = fmaf(xv.x, wv.x, acc[0][0]); acc[0][1] = fmaf(xv.x, wv.y, acc[0][1]);
        acc[0][2] = fmaf(xv.x, wv.z, acc[0][2]); acc[0][3] = fmaf(xv.x, wv.w, acc[0][3]);
        acc[1][0] = fmaf(xv.y, wv.x, acc[1][0]); acc[1][1] = fmaf(xv.y, wv.y, acc[1][1]);
        acc[1][2] = fmaf(xv.y, wv.z, acc[1][2]); acc[1][3] = fmaf(xv.y, wv.w, acc[1][3]);
        acc[2][0] = fmaf(xv.z, wv.x, acc[2][0]); acc[2][1] = fmaf(xv.z, wv.y, acc[2][1]);
        acc[2][2] = fmaf(xv.z, wv.z, acc[2][2]); acc[2][3] = fmaf(xv.z, wv.w, acc[2][3]);
        acc[3][0] = fmaf(xv.w, wv.x, acc[3][0]); acc[3][1] = fmaf(xv.w, wv.y, acc[3][1]);
        acc[3][2] = fmaf(xv.w, wv.z, acc[3][2]); acc[3][3] = fmaf(xv.w, wv.w, acc[3][3]);
    }

    // sigmoid -> fp16 pack -> 8B store per node row segment
    #pragma unroll
    for (int a = 0; a < 4; a++) {
        int n_g = nb + n0 + a;
        if (n_g < N_NODES) {
            float s0 = 1.0f / (1.0f + __expf(-acc[a][0]));
            float s1 = 1.0f / (1.0f + __expf(-acc[a][1]));
            float s2 = 1.0f / (1.0f + __expf(-acc[a][2]));
            float s3 = 1.0f / (1.0f + __expf(-acc[a][3]));
            __half2 h0 = __floats2half2_rn(s0, s1);
            __half2 h1 = __floats2half2_rn(s2, s3);
            uint2 pk;
            pk.x = *reinterpret_cast<unsigned int*>(&h0);
            pk.y = *reinterpret_cast<unsigned int*>(&h1);
            *reinterpret_cast<uint2*>(&g_nemb[n_g * D + j0]) = pk;
        }
    }
}
#undef S

// ---------------------------------------------------------------------------
// k3: edge output: out[e] = (nemb[src] + nemb[dst]) * 0.5
// 8 threads per edge slot, TWO edges per thread. Gathers use __ldcg (L2-only:
// nemb has no L1 reuse, skip fill wavefronts); stores use __stwt
// (write-through: the 205MB out stream never occupies L2, leaving the whole
// L2 to the g_nemb gather working set).
// ---------------------------------------------------------------------------
__device__ __forceinline__ void edge_avg(uint4 ha, uint4 hd, float4& o0, float4& o1) {
    const __half2* pa = reinterpret_cast<const __half2*>(&ha);
    const __half2* pd = reinterpret_cast<const __half2*>(&hd);
    float2 a0 = __half22float2(pa[0]); float2 d0 = __half22float2(pd[0]);
    float2 a1 = __half22float2(pa[1]); float2 d1 = __half22float2(pd[1]);
    o0 = make_float4((a0.x + d0.x) * 0.5f, (a0.y + d0.y) * 0.5f,
                     (a1.x + d1.x) * 0.5f, (a1.y + d1.y) * 0.5f);
    float2 a2 = __half22float2(pa[2]); float2 d2 = __half22float2(pd[2]);
    float2 a3 = __half22float2(pa[3]); float2 d3 = __half22float2(pd[3]);
    o1 = make_float4((a2.x + d2.x) * 0.5f, (a2.y + d2.y) * 0.5f,
                     (a3.x + d3.x) * 0.5f, (a3.y + d3.y) * 0.5f);
}

__global__ void k_edge(const void* __restrict__ edge_index,
                       float* __restrict__ out) {
    const int HALF = N_EDGES / 2;   // 400000
    int t = blockIdx.x * blockDim.x + threadIdx.x;
    if (t >= HALF * 8) return;
    int is64 = g_is64;
    int e0 = t >> 3;
    int c  = t & 7;
    int e1 = e0 + HALF;

    int s0 = load_index(edge_index, e0, is64);
    int d0 = load_index(edge_index, N_EDGES + e0, is64);
    int s1 = load_index(edge_index, e1, is64);
    int d1 = load_index(edge_index, N_EDGES + e1, is64);

    uint4 zero = make_uint4(0u, 0u, 0u, 0u);
    uint4 ha0 = zero, hd0 = zero, ha1 = zero, hd1 = zero;
    const uint4* nb = reinterpret_cast<const uint4*>(g_nemb);
    // 4 independent L2 gathers in flight before any consumption
    if ((unsigned)s0 < N_NODES) ha0 = __ldcg(nb + (size_t)s0 * 8 + c);
    if ((unsigned)d0 < N_NODES) hd0 = __ldcg(nb + (size_t)d0 * 8 + c);
    if ((unsigned)s1 < N_NODES) ha1 = __ldcg(nb + (size_t)s1 * 8 + c);
    if ((unsigned)d1 < N_NODES) hd1 = __ldcg(nb + (size_t)d1 * 8 + c);

    float4 o0, o1;
    edge_avg(ha0, hd0, o0, o1);
    float4* po0 = reinterpret_cast<float4*>(out) + (size_t)e0 * 16 + c * 2;
    __stwt(po0 + 0, o0);
    __stwt(po0 + 1, o1);

    edge_avg(ha1, hd1, o0, o1);
    float4* po1 = reinterpret_cast<float4*>(out) + (size_t)e1 * 16 + c * 2;
    __stwt(po1 + 0, o0);
    __stwt(po1 + 1, o1);
}

// ---------------------------------------------------------------------------
// Inputs identified BY ELEMENT COUNT (robust to metadata ordering):
//   edge_attr  f32     [800000,64] -> 51,200,000
//   edge_index i32/i64 [2,800000]  ->  1,600,000
//   node_attr  f32     [50000,64]  ->  3,200,000
//   W          f32     [64,64]     ->      4,096
//   b          f32     [64]        ->         64
// Output: f32 [800000,64]
// ---------------------------------------------------------------------------
extern "C" void kernel_launch(void* const* d_in, const int* in_sizes, int n_in,
                              void* d_out, int out_size) {
    const float* edge_attr  = nullptr;
    const void*  edge_index = nullptr;
    const float* node_attr  = nullptr;
    const float* W          = nullptr;
    const float* b          = nullptr;

    int c32[4]; int n32 = 0;
    for (int i = 0; i < n_in; i++) {
        switch (in_sizes[i]) {
            case 51200000: edge_attr  = (const float*)d_in[i]; break;
            case 1600000:  edge_index = d_in[i];               break;
            case 3200000:  if (n32 < 4) c32[n32++] = i;        break;
            case 4096:     W          = (const float*)d_in[i]; break;
            case 64:       b          = (const float*)d_in[i]; break;
            default: break;
        }
    }
    if (n32 == 1) {
        node_attr = (const float*)d_in[c32[0]];
    } else if (n32 >= 2) {
        if (!edge_index) { edge_index = d_in[c32[0]]; node_attr = (const float*)d_in[c32[1]]; }
        else             { node_attr  = (const float*)d_in[c32[0]]; }
    }
    float* out = (float*)d_out;

    const int ZERO4 = (N_NODES * D) / 4 + N_NODES / 4;   // 812500
    k_zero<<<(ZERO4 + 255) / 256, 256>>>((const int2*)edge_index);

    const int SCAT = (N_EDGES / 2) * 16;                  // 6.4M
    k_scatter<<<(SCAT + 255) / 256, 256>>>(edge_attr, edge_index);

    k_node<<<(N_NODES + 63) / 64, 256>>>(node_attr, W, b);

    const int EDG = (N_EDGES / 2) * 8;                    // 3.2M
    k_edge<<<(EDG + 255) / 256, 256>>>(edge_index, out);
}